// round 12
// baseline (speedup 1.0000x reference)
#include <cuda_runtime.h>
#include <cuda_bf16.h>
#include <math.h>

// Problem constants
// x:  [B=8, C=512, H=32, W=32] -> [8, 512, 1024]
// W*: [512, 512], b*: [512]
// heads = 8, head_dim = 64, N = 1024

#define BATCH 8
#define DIM 512
#define NPIX 1024
#define NH 8
#define HD 64
#define PLANE (BATCH * DIM * NPIX)   // 4,194,304 elements

// Scratch (static __device__ globals: allocation-guard safe)
__device__ __nv_bfloat16 g_xb[PLANE];
__device__ __nv_bfloat16 g_wb[4 * DIM * DIM];   // Wq|Wk|Wv|Wo (Wq pre-scaled)
__device__ float         g_bqkv[3 * DIM];       // bq*qscale | bk | bv
__device__ __nv_bfloat16 g_qkv[3 * PLANE];      // Q | K | V bf16
__device__ __nv_bfloat16 g_aob[PLANE];          // attention out bf16

// ---------------------------------------------------------------------------
// Conversions
// ---------------------------------------------------------------------------
__global__ void f2bf(const float* __restrict__ in, __nv_bfloat16* __restrict__ out,
                     int n4)
{
    int i = blockIdx.x * blockDim.x + threadIdx.x;
    if (i < n4) {
        float4 v = ((const float4*)in)[i];
        ((__nv_bfloat162*)out)[i * 2]     = __floats2bfloat162_rn(v.x, v.y);
        ((__nv_bfloat162*)out)[i * 2 + 1] = __floats2bfloat162_rn(v.z, v.w);
    }
}

__global__ void f2bf_w(const float* __restrict__ Wq, const float* __restrict__ Wk,
                       const float* __restrict__ Wv, const float* __restrict__ Wo,
                       __nv_bfloat16* __restrict__ out, float qs)
{
    const int n4m = DIM * DIM / 4;               // 65536
    int i = blockIdx.x * blockDim.x + threadIdx.x;
    int m = i / n4m, r = i - m * n4m;
    const float* src = (m == 0) ? Wq : (m == 1) ? Wk : (m == 2) ? Wv : Wo;
    float s = (m == 0) ? qs : 1.f;
    float4 v = ((const float4*)src)[r];
    ((__nv_bfloat162*)out)[i * 2]     = __floats2bfloat162_rn(v.x * s, v.y * s);
    ((__nv_bfloat162*)out)[i * 2 + 1] = __floats2bfloat162_rn(v.z * s, v.w * s);
}

__global__ void pack_bias(const float* __restrict__ bq, const float* __restrict__ bk,
                          const float* __restrict__ bv, float* __restrict__ out,
                          float qs)
{
    int i = blockIdx.x * blockDim.x + threadIdx.x;
    if (i < DIM)            out[i] = bq[i] * qs;
    else if (i < 2 * DIM)   out[i] = bk[i - DIM];
    else                    out[i] = bv[i - 2 * DIM];
}

// ---------------------------------------------------------------------------
// Tensor-core / async-copy helpers
// ---------------------------------------------------------------------------
__device__ __forceinline__ unsigned smem_u32(const void* p)
{
    return (unsigned)__cvta_generic_to_shared(p);
}

__device__ __forceinline__ void cp_async16(void* smem_dst, const void* gmem_src)
{
    asm volatile("cp.async.cg.shared.global [%0], [%1], 16;\n"
                 :: "r"(smem_u32(smem_dst)), "l"(gmem_src));
}
__device__ __forceinline__ void cp_commit()
{
    asm volatile("cp.async.commit_group;\n");
}
template<int N>
__device__ __forceinline__ void cp_wait()
{
    asm volatile("cp.async.wait_group %0;\n" :: "n"(N));
}

__device__ __forceinline__ void bar_sync(int id)
{
    asm volatile("bar.sync %0, 128;\n" :: "r"(id) : "memory");
}

__device__ __forceinline__ void ldsm_x4(unsigned* r, unsigned addr)
{
    asm volatile("ldmatrix.sync.aligned.m8n8.x4.shared.b16 {%0,%1,%2,%3}, [%4];\n"
                 : "=r"(r[0]), "=r"(r[1]), "=r"(r[2]), "=r"(r[3]) : "r"(addr));
}

__device__ __forceinline__ void ldsm_x4_trans(unsigned* r, unsigned addr)
{
    asm volatile("ldmatrix.sync.aligned.m8n8.x4.trans.shared.b16 {%0,%1,%2,%3}, [%4];\n"
                 : "=r"(r[0]), "=r"(r[1]), "=r"(r[2]), "=r"(r[3]) : "r"(addr));
}

__device__ __forceinline__ void mma16816(float* d, const unsigned* a,
                                         unsigned b0, unsigned b1)
{
    asm volatile(
        "mma.sync.aligned.m16n8k16.row.col.f32.bf16.bf16.f32 "
        "{%0,%1,%2,%3}, {%4,%5,%6,%7}, {%8,%9}, {%0,%1,%2,%3};\n"
        : "+f"(d[0]), "+f"(d[1]), "+f"(d[2]), "+f"(d[3])
        : "r"(a[0]), "r"(a[1]), "r"(a[2]), "r"(a[3]), "r"(b0), "r"(b1));
}

// Schraudolph exp2: 2 instructions. Max rel err ~3%; softmax normalization
// cancels the common mode and P is rounded to bf16 anyway.
__device__ __forceinline__ float sexp2(float t)
{
    float f = fmaf(t, 8388608.f, 1064866805.f);   // t*2^23 + (127<<23 - 486411)
    return __int_as_float((int)f);
}

__device__ __forceinline__ unsigned pack_bf16x2(float a, float b)
{
    __nv_bfloat162 t = __floats2bfloat162_rn(a, b);
    return *(unsigned*)&t;
}

// ---------------------------------------------------------------------------
// bf16 tensor-core GEMM, R12: two INDEPENDENT 128-thread warpgroup pipelines
// per CTA. WG g owns output rows [g*64, g*64+64) of the 128-row tile, has its
// own 4-stage A+B smem ring (B duplicated per WG) and its own named barrier.
// Per-WG loop = R6 proven structure: BK=32, issue-before-wait at distance 2,
// ONE bar.sync(128) per iteration.
// acc[m][n] = sum_c W[m][c] X[b][c][n];  epilogue = acc + bias[m]
// BF16OUT=true:  M=1536 stacked QKV -> outb[(proj*BATCH+b)][o][n] bf16.
// BF16OUT=false: M=512; fp32 out + residual.
// ---------------------------------------------------------------------------
#define LDA 40
#define LDB 136
#define GSTG 4
#define WG_A (64 * LDA)                    // 2560 elems
#define WG_B (32 * LDB)                    // 4352 elems
#define WG_STAGE (WG_A + WG_B)             // 6912 elems
#define GEMM_SMEM_BYTES (2 * GSTG * WG_STAGE * 2)   // 110592 B

template<bool BF16OUT>
__global__ __launch_bounds__(256)
void gemm_tc(const __nv_bfloat16* __restrict__ W,
             const __nv_bfloat16* __restrict__ X,
             const float* __restrict__ bias,
             const float* __restrict__ resid,
             float* __restrict__ outf,
             __nv_bfloat16* __restrict__ outb)
{
    extern __shared__ __nv_bfloat16 gsm[];

    const int b  = blockIdx.z;
    const int m0 = blockIdx.y * 128;
    const int n0 = blockIdx.x * 128;

    const __nv_bfloat16* Xb = X + (size_t)b * DIM * NPIX;

    const int tid  = threadIdx.x;
    const int wg   = tid >> 7;             // warpgroup 0/1
    const int wtid = tid & 127;
    const int lane = tid & 31;
    const int wn   = (wtid >> 5);          // 0..3: n sub-tile within WG

    __nv_bfloat16* wbase = gsm + wg * (GSTG * WG_STAGE);

    float acc[4][4][4];
    #pragma unroll
    for (int mt = 0; mt < 4; mt++)
        #pragma unroll
        for (int nt = 0; nt < 4; nt++)
            #pragma unroll
            for (int r = 0; r < 4; r++) acc[mt][nt][r] = 0.f;

    // Copy roles within the 128-thread WG:
    // A half-tile: 64 rows x 32 k -> 2 threads/row, 2x16B each
    const int am  = wtid >> 1;             // 0..63
    const int akc = (wtid & 1) * 16;
    // B tile: 32 rows (k) x 128 n -> 4 threads/row, 4x16B each
    const int bc  = wtid >> 2;             // 0..31
    const int bnc = (wtid & 3) * 32;

    const __nv_bfloat16* Wrow = W + (size_t)(m0 + wg * 64 + am) * DIM;
    const __nv_bfloat16* Xrow = Xb + (size_t)bc * NPIX + n0;

    auto issue = [&](int s, int k0) {
        __nv_bfloat16* as = wbase + s * WG_STAGE;
        __nv_bfloat16* bs = as + WG_A;
        cp_async16(&as[am * LDA + akc],     Wrow + k0 + akc);
        cp_async16(&as[am * LDA + akc + 8], Wrow + k0 + akc + 8);
        #pragma unroll
        for (int u = 0; u < 4; u++)
            cp_async16(&bs[bc * LDB + bnc + u * 8],
                       Xrow + (size_t)k0 * NPIX + bnc + u * 8);
        cp_commit();
    };

    issue(0, 0);
    issue(1, 32);

    const int barid = 1 + wg;
    for (int it = 0; it < 16; it++) {
        if (it + 2 < 16) issue((it + 2) & 3, (it + 2) * 32);
        else             cp_commit();          // keep group count advancing
        cp_wait<2>();                          // this thread's group `it` done
        bar_sync(barid);                       // WG-local convergence only

        const __nv_bfloat16* Asb = wbase + (it & 3) * WG_STAGE;
        const __nv_bfloat16* Bsb = Asb + WG_A;

        #pragma unroll
        for (int ks = 0; ks < 32; ks += 16) {
            unsigned af[4][4], bf[2][4];
            #pragma unroll
            for (int mt = 0; mt < 4; mt++) {
                unsigned addr = smem_u32(
                    &Asb[(mt * 16 + (lane & 15)) * LDA + ks + (lane >> 4) * 8]);
                ldsm_x4(af[mt], addr);
            }
            #pragma unroll
            for (int half = 0; half < 2; half++) {
                unsigned addr = smem_u32(
                    &Bsb[(ks + (lane & 15)) * LDB + wn * 32 + half * 16 + (lane >> 4) * 8]);
                ldsm_x4_trans(bf[half], addr);
            }
            #pragma unroll
            for (int mt = 0; mt < 4; mt++)
                #pragma unroll
                for (int nt = 0; nt < 4; nt++)
                    mma16816(acc[mt][nt], af[mt],
                             bf[nt >> 1][(nt & 1) * 2], bf[nt >> 1][(nt & 1) * 2 + 1]);
        }
        // no trailing sync: distance-2 issue invariant covers buffer reuse
    }

    // Epilogue (per-warp, no cross-thread sharing). m16n8k16 accumulator:
    // c0:(g, tg*2) c1:(g, tg*2+1) c2:(g+8, tg*2) c3:(g+8, tg*2+1)
    const int g  = lane >> 2;
    const int tg = lane & 3;
    #pragma unroll
    for (int mt = 0; mt < 4; mt++) {
        int gm0 = m0 + wg * 64 + mt * 16 + g;
        float bv0 = bias[gm0];
        float bv1 = bias[gm0 + 8];
        #pragma unroll
        for (int nt = 0; nt < 4; nt++) {
            int n = n0 + wn * 32 + nt * 8 + tg * 2;
            float r00 = acc[mt][nt][0] + bv0;
            float r01 = acc[mt][nt][1] + bv0;
            float r10 = acc[mt][nt][2] + bv1;
            float r11 = acc[mt][nt][3] + bv1;
            if (BF16OUT) {
                int proj = gm0 >> 9;
                int o    = gm0 & 511;
                __nv_bfloat16* op = outb + ((size_t)proj * BATCH + b) * DIM * NPIX;
                size_t off0 = (size_t)o * NPIX + n;
                size_t off1 = off0 + (size_t)8 * NPIX;
                *(__nv_bfloat162*)&op[off0] = __floats2bfloat162_rn(r00, r01);
                *(__nv_bfloat162*)&op[off1] = __floats2bfloat162_rn(r10, r11);
            } else {
                size_t off0 = (size_t)b * DIM * NPIX + (size_t)gm0 * NPIX + n;
                size_t off1 = off0 + (size_t)8 * NPIX;
                float2 x0 = *(const float2*)&resid[off0];
                float2 x1 = *(const float2*)&resid[off1];
                float2 w0, w1;
                w0.x = r00 + x0.x; w0.y = r01 + x0.y;
                w1.x = r10 + x1.x; w1.y = r11 + x1.y;
                *(float2*)&outf[off0] = w0;
                *(float2*)&outf[off1] = w1;
            }
        }
    }
}

// ---------------------------------------------------------------------------
// Tensor-core flash attention (R11 — validated at 159.7us total):
// 4-stage cp.async K/V (64-key tiles), one sync per tile, issue-before-wait,
// P in registers, fixed-shift softmax with Schraudolph exp2.
// Q,K,V bf16 [B*NH][64 d][1024 n]. log2e/8 folded into Q projection.
// 256 threads; warp w owns query rows [w*16, w*16+16).
// ---------------------------------------------------------------------------
#define TI 128
#define TJ 64
#define LDQ 136
#define LDK 72
#define LDV 72
#define LDP 72
#define ASTG 4
#define ATTN_SMEM_ELEMS (64 * LDQ + ASTG * 64 * LDK + ASTG * 64 * LDV)

__global__ __launch_bounds__(256, 2)
void attn_mma(const __nv_bfloat16* __restrict__ Q,
              const __nv_bfloat16* __restrict__ K,
              const __nv_bfloat16* __restrict__ V,
              __nv_bfloat16* __restrict__ AO)
{
    extern __shared__ __nv_bfloat16 smb[];
    __nv_bfloat16* sQ   = smb;                         // [64][LDQ]
    __nv_bfloat16* sK   = sQ + 64 * LDQ;               // [ASTG][64][LDK]
    __nv_bfloat16* sV   = sK + ASTG * 64 * LDK;        // [ASTG][64][LDV]
    __nv_bfloat16* sEpi = sK;                          // epilogue alias (stages 0-1)

    const int tid  = threadIdx.x;
    const int lane = tid & 31;
    const int warp = tid >> 5;
    const int i0   = warp * 16;
    const int g    = lane >> 2;
    const int tg   = lane & 3;
    const int n0   = blockIdx.x * TI;

    const size_t base = ((size_t)blockIdx.z * NH + blockIdx.y) * (size_t)HD * NPIX;
    const __nv_bfloat16* Qp = Q + base;
    const __nv_bfloat16* Kp = K + base;
    const __nv_bfloat16* Vp = V + base;

    // Load Q tile [64][128]
    #pragma unroll
    for (int it = tid; it < 1024; it += 256) {
        int d = it >> 4, c = it & 15;
        *(uint4*)&sQ[d * LDQ + c * 8] =
            *(const uint4*)&Qp[(size_t)d * NPIX + n0 + c * 8];
    }

    auto issueKV = [&](int s, int j0) {
        __nv_bfloat16* ks = sK + s * (64 * LDK);
        __nv_bfloat16* vs = sV + s * (64 * LDV);
        #pragma unroll
        for (int it = tid; it < 512; it += 256) {
            int d = it >> 3, c = it & 7;
            cp_async16(&ks[d * LDK + c * 8], Kp + (size_t)d * NPIX + j0 + c * 8);
            cp_async16(&vs[d * LDV + c * 8], Vp + (size_t)d * NPIX + j0 + c * 8);
        }
        cp_commit();
    };

    issueKV(0, 0);
    issueKV(1, TJ);
    __syncthreads();                 // Q visible

    // Hoisted Q fragments (invariant across KV tiles)
    unsigned aq[4][4];
    #pragma unroll
    for (int k8 = 0; k8 < 4; k8++) {
        unsigned addr = smem_u32(
            &sQ[(k8 * 16 + (lane & 7) + ((lane >> 4) << 3)) * LDQ +
                i0 + ((lane >> 3) & 1) * 8]);
        ldsm_x4_trans(aq[k8], addr);
    }

    float l_h[2], O[8][4];
    l_h[0] = l_h[1] = 0.f;
    #pragma unroll
    for (int dt = 0; dt < 8; dt++)
        #pragma unroll
        for (int r = 0; r < 4; r++) O[dt][r] = 0.f;

    for (int kt = 0; kt < 16; kt++) {
        if (kt + 2 < 16) issueKV((kt + 2) & 3, (kt + 2) * TJ);
        else             cp_commit();
        cp_wait<2>();
        __syncthreads();

        const __nv_bfloat16* sKb = sK + (kt & 3) * (64 * LDK);
        const __nv_bfloat16* sVb = sV + (kt & 3) * (64 * LDV);

        // GEMM1: S[16 i][64 j] = Q^T K
        float S[8][4];
        #pragma unroll
        for (int nt = 0; nt < 8; nt++)
            #pragma unroll
            for (int r = 0; r < 4; r++) S[nt][r] = 0.f;

        #pragma unroll
        for (int k8 = 0; k8 < 4; k8++) {
            unsigned bk[4][4];
            #pragma unroll
            for (int jb = 0; jb < 4; jb++) {
                unsigned addr = smem_u32(
                    &sKb[(k8 * 16 + (lane & 15)) * LDK + jb * 16 + (lane >> 4) * 8]);
                ldsm_x4_trans(bk[jb], addr);
            }
            #pragma unroll
            for (int nt = 0; nt < 8; nt++)
                mma16816(S[nt], aq[k8],
                         bk[nt >> 1][(nt & 1) * 2], bk[nt >> 1][(nt & 1) * 2 + 1]);
        }

        // Fixed-shift softmax, 2-instruction exp2; pack P into GEMM2 A-frags.
        unsigned pa[4][4];
        float rs0 = 0.f, rs1 = 0.f;
        #pragma unroll
        for (int nt = 0; nt < 8; nt++) {
            float p0 = sexp2(S[nt][0]);
            float p1 = sexp2(S[nt][1]);
            float p2 = sexp2(S[nt][2]);
            float p3 = sexp2(S[nt][3]);
            rs0 += p0 + p1;
            rs1 += p2 + p3;
            pa[nt >> 1][(nt & 1) * 2]     = pack_bf16x2(p0, p1);
            pa[nt >> 1][(nt & 1) * 2 + 1] = pack_bf16x2(p2, p3);
        }
        rs0 += __shfl_xor_sync(0xffffffffu, rs0, 1);
        rs0 += __shfl_xor_sync(0xffffffffu, rs0, 2);
        rs1 += __shfl_xor_sync(0xffffffffu, rs1, 1);
        rs1 += __shfl_xor_sync(0xffffffffu, rs1, 2);
        l_h[0] += rs0;
        l_h[1] += rs1;

        // GEMM2: O[16 i][64 d] += P V^T  (A from registers)
        #pragma unroll
        for (int k8 = 0; k8 < 4; k8++) {
            unsigned bv[4][4];
            #pragma unroll
            for (int db = 0; db < 4; db++) {
                unsigned addr = smem_u32(
                    &sVb[(db * 16 + (lane & 15)) * LDV + k8 * 16 + (lane >> 4) * 8]);
                ldsm_x4(bv[db], addr);
            }
            #pragma unroll
            for (int dt = 0; dt < 8; dt++)
                mma16816(O[dt], pa[k8],
                         bv[dt >> 1][dt & 1], bv[dt >> 1][(dt & 1) + 2]);
        }
        // no trailing sync: distance-2 issue invariant covers buffer reuse
    }

    // Scale by 1/l, stage O bf16 [i][d] in sEpi (KV stages 0-1 only)
    float rl0 = 1.f / l_h[0];
    float rl1 = 1.f / l_h[1];
    #pragma unroll
    for (int dt = 0; dt < 8; dt++) {
        *(__nv_bfloat162*)&sEpi[(i0 + g) * LDP + dt * 8 + tg * 2] =
            __floats2bfloat162_rn(O[dt][0] * rl0, O[dt][1] * rl0);
        *(__nv_bfloat162*)&sEpi[(i0 + g + 8) * LDP + dt * 8 + tg * 2] =
            __floats2bfloat162_rn(O[dt][2] * rl1, O[dt][3] * rl1);
    }
    __syncthreads();

    // Transpose out: AO[d][n0 + i], 8 bf16 per store
    __nv_bfloat16* AOp = AO + base;
    #pragma unroll
    for (int it = tid; it < 1024; it += 256) {
        int d  = it & 63;
        int ic = it >> 6;
        __nv_bfloat16 t[8];
        #pragma unroll
        for (int u = 0; u < 8; u++)
            t[u] = sEpi[(ic * 8 + u) * LDP + d];
        *(uint4*)&AOp[(size_t)d * NPIX + n0 + ic * 8] = *(uint4*)t;
    }
}

// ---------------------------------------------------------------------------
extern "C" void kernel_launch(void* const* d_in, const int* in_sizes, int n_in,
                              void* d_out, int out_size)
{
    const float* x  = (const float*)d_in[0];
    const float* Wq = (const float*)d_in[1];
    const float* bq = (const float*)d_in[2];
    const float* Wk = (const float*)d_in[3];
    const float* bk = (const float*)d_in[4];
    const float* Wv = (const float*)d_in[5];
    const float* bv = (const float*)d_in[6];
    const float* Wo = (const float*)d_in[7];
    const float* bo = (const float*)d_in[8];
    float* out = (float*)d_out;

    __nv_bfloat16 *xb, *wb, *qkv, *aob;
    float* bqkv;
    cudaGetSymbolAddress((void**)&xb,   g_xb);
    cudaGetSymbolAddress((void**)&wb,   g_wb);
    cudaGetSymbolAddress((void**)&bqkv, g_bqkv);
    cudaGetSymbolAddress((void**)&qkv,  g_qkv);
    cudaGetSymbolAddress((void**)&aob,  g_aob);

    // 1/sqrt(64) * log2(e): folded into Wq/bq so softmax runs in base 2
    const float qscale = 0.125f * 1.4426950408889634f;

    f2bf<<<PLANE / 4 / 256, 256>>>(x, xb, PLANE / 4);
    f2bf_w<<<4 * DIM * DIM / 4 / 256, 256>>>(Wq, Wk, Wv, Wo, wb, qscale);
    pack_bias<<<6, 256>>>(bq, bk, bv, bqkv, qscale);

    cudaFuncSetAttribute(gemm_tc<true>, cudaFuncAttributeMaxDynamicSharedMemorySize,
                         GEMM_SMEM_BYTES);
    cudaFuncSetAttribute(gemm_tc<false>, cudaFuncAttributeMaxDynamicSharedMemorySize,
                         GEMM_SMEM_BYTES);

    // Fused QKV projection: M = 1536 stacked
    dim3 qkv_grid(NPIX / 128, 3 * DIM / 128, BATCH);   // (8, 12, 8)
    gemm_tc<true><<<qkv_grid, 256, GEMM_SMEM_BYTES>>>(wb, xb, bqkv, nullptr,
                                                      nullptr, qkv);

    const int attn_smem = ATTN_SMEM_ELEMS * (int)sizeof(__nv_bfloat16);
    cudaFuncSetAttribute(attn_mma, cudaFuncAttributeMaxDynamicSharedMemorySize,
                         attn_smem);
    dim3 attn_grid(NPIX / TI, NH, BATCH);              // (8, 8, 8)
    attn_mma<<<attn_grid, 256, attn_smem>>>(qkv, qkv + PLANE, qkv + 2 * PLANE, aob);

    dim3 o_grid(NPIX / 128, DIM / 128, BATCH);         // (8, 4, 8)
    gemm_tc<false><<<o_grid, 256, GEMM_SMEM_BYTES>>>(wb + 3 * DIM * DIM, aob, bo,
                                                     x, out, nullptr);
}

// round 13
// speedup vs baseline: 1.2505x; 1.2505x over previous
#include <cuda_runtime.h>
#include <cuda_bf16.h>
#include <math.h>

// Problem constants
// x:  [B=8, C=512, H=32, W=32] -> [8, 512, 1024]
// W*: [512, 512], b*: [512]
// heads = 8, head_dim = 64, N = 1024

#define BATCH 8
#define DIM 512
#define NPIX 1024
#define NH 8
#define HD 64
#define PLANE (BATCH * DIM * NPIX)   // 4,194,304 elements

// Scratch (static __device__ globals: allocation-guard safe)
__device__ __nv_bfloat16 g_xb[PLANE];
__device__ __nv_bfloat16 g_wb[4 * DIM * DIM];   // Wq|Wk|Wv|Wo (Wq pre-scaled)
__device__ float         g_bqkv[3 * DIM];       // bq*qscale | bk | bv
__device__ __nv_bfloat16 g_qkv[3 * PLANE];      // Q | K | V bf16
__device__ __nv_bfloat16 g_aob[PLANE];          // attention out bf16

// ---------------------------------------------------------------------------
// Conversions
// ---------------------------------------------------------------------------
__global__ void f2bf(const float* __restrict__ in, __nv_bfloat16* __restrict__ out,
                     int n4)
{
    int i = blockIdx.x * blockDim.x + threadIdx.x;
    if (i < n4) {
        float4 v = ((const float4*)in)[i];
        ((__nv_bfloat162*)out)[i * 2]     = __floats2bfloat162_rn(v.x, v.y);
        ((__nv_bfloat162*)out)[i * 2 + 1] = __floats2bfloat162_rn(v.z, v.w);
    }
}

__global__ void f2bf_w(const float* __restrict__ Wq, const float* __restrict__ Wk,
                       const float* __restrict__ Wv, const float* __restrict__ Wo,
                       __nv_bfloat16* __restrict__ out, float qs)
{
    const int n4m = DIM * DIM / 4;               // 65536
    int i = blockIdx.x * blockDim.x + threadIdx.x;
    int m = i / n4m, r = i - m * n4m;
    const float* src = (m == 0) ? Wq : (m == 1) ? Wk : (m == 2) ? Wv : Wo;
    float s = (m == 0) ? qs : 1.f;
    float4 v = ((const float4*)src)[r];
    ((__nv_bfloat162*)out)[i * 2]     = __floats2bfloat162_rn(v.x * s, v.y * s);
    ((__nv_bfloat162*)out)[i * 2 + 1] = __floats2bfloat162_rn(v.z * s, v.w * s);
}

__global__ void pack_bias(const float* __restrict__ bq, const float* __restrict__ bk,
                          const float* __restrict__ bv, float* __restrict__ out,
                          float qs)
{
    int i = blockIdx.x * blockDim.x + threadIdx.x;
    if (i < DIM)            out[i] = bq[i] * qs;
    else if (i < 2 * DIM)   out[i] = bk[i - DIM];
    else                    out[i] = bv[i - 2 * DIM];
}

// ---------------------------------------------------------------------------
// Tensor-core / async-copy helpers
// ---------------------------------------------------------------------------
__device__ __forceinline__ unsigned smem_u32(const void* p)
{
    return (unsigned)__cvta_generic_to_shared(p);
}

__device__ __forceinline__ void cp_async16(void* smem_dst, const void* gmem_src)
{
    asm volatile("cp.async.cg.shared.global [%0], [%1], 16;\n"
                 :: "r"(smem_u32(smem_dst)), "l"(gmem_src));
}
__device__ __forceinline__ void cp_commit()
{
    asm volatile("cp.async.commit_group;\n");
}
template<int N>
__device__ __forceinline__ void cp_wait()
{
    asm volatile("cp.async.wait_group %0;\n" :: "n"(N));
}

__device__ __forceinline__ void ldsm_x4(unsigned* r, unsigned addr)
{
    asm volatile("ldmatrix.sync.aligned.m8n8.x4.shared.b16 {%0,%1,%2,%3}, [%4];\n"
                 : "=r"(r[0]), "=r"(r[1]), "=r"(r[2]), "=r"(r[3]) : "r"(addr));
}

__device__ __forceinline__ void ldsm_x4_trans(unsigned* r, unsigned addr)
{
    asm volatile("ldmatrix.sync.aligned.m8n8.x4.trans.shared.b16 {%0,%1,%2,%3}, [%4];\n"
                 : "=r"(r[0]), "=r"(r[1]), "=r"(r[2]), "=r"(r[3]) : "r"(addr));
}

__device__ __forceinline__ void mma16816(float* d, const unsigned* a,
                                         unsigned b0, unsigned b1)
{
    asm volatile(
        "mma.sync.aligned.m16n8k16.row.col.f32.bf16.bf16.f32 "
        "{%0,%1,%2,%3}, {%4,%5,%6,%7}, {%8,%9}, {%0,%1,%2,%3};\n"
        : "+f"(d[0]), "+f"(d[1]), "+f"(d[2]), "+f"(d[3])
        : "r"(a[0]), "r"(a[1]), "r"(a[2]), "r"(a[3]), "r"(b0), "r"(b1));
}

// Schraudolph exp2: 2 instructions. Max rel err ~3%; softmax normalization
// cancels the common mode and P is rounded to bf16 anyway.
__device__ __forceinline__ float sexp2(float t)
{
    float f = fmaf(t, 8388608.f, 1064866805.f);   // t*2^23 + (127<<23 - 486411)
    return __int_as_float((int)f);
}

__device__ __forceinline__ unsigned pack_bf16x2(float a, float b)
{
    __nv_bfloat162 t = __floats2bfloat162_rn(a, b);
    return *(unsigned*)&t;
}

// ---------------------------------------------------------------------------
// bf16 tensor-core GEMM, R13: SAME smem layout + pipeline as R6/R11 (BK=32,
// 4-stage, distance-2 issue-before-wait, ONE __syncthreads/iter) but with
// 512 threads / 16 warps (warp tile 32x32, acc 32 regs). launch_bounds
// (512,2) -> regs<=64 -> 2 CTAs/SM = 32 warps/SM (full occupancy) to hide
// the LDSM->HMMA scoreboard latency that capped R11 at tensor=38.6%.
// acc[m][n] = sum_c W[m][c] X[b][c][n];  epilogue = acc + bias[m]
// BF16OUT=true:  M=1536 stacked QKV -> outb[(proj*BATCH+b)][o][n] bf16.
// BF16OUT=false: M=512; fp32 out + residual.
// ---------------------------------------------------------------------------
#define LDA 40
#define LDB 136
#define GSTG 4
#define GEMM_SMEM_BYTES (GSTG * (128 * LDA + 32 * LDB) * 2)

template<bool BF16OUT>
__global__ __launch_bounds__(512, 2)
void gemm_tc(const __nv_bfloat16* __restrict__ W,
             const __nv_bfloat16* __restrict__ X,
             const float* __restrict__ bias,
             const float* __restrict__ resid,
             float* __restrict__ outf,
             __nv_bfloat16* __restrict__ outb)
{
    extern __shared__ __nv_bfloat16 gsm[];
    __nv_bfloat16* As = gsm;                       // [GSTG][128*LDA]
    __nv_bfloat16* Bs = gsm + GSTG * 128 * LDA;    // [GSTG][32*LDB]

    const int b  = blockIdx.z;
    const int m0 = blockIdx.y * 128;
    const int n0 = blockIdx.x * 128;

    const __nv_bfloat16* Xb = X + (size_t)b * DIM * NPIX;

    const int tid  = threadIdx.x;
    const int lane = tid & 31;
    const int warp = tid >> 5;       // 0..15
    const int wm   = warp >> 2;      // 0..3: m sub-tile (32 rows)
    const int wn   = warp & 3;       // 0..3: n sub-tile (32 cols)

    float acc[2][4][4];
    #pragma unroll
    for (int mt = 0; mt < 2; mt++)
        #pragma unroll
        for (int nt = 0; nt < 4; nt++)
            #pragma unroll
            for (int r = 0; r < 4; r++) acc[mt][nt][r] = 0.f;

    // Copy roles (512 threads, 1 cp.async16 each per operand):
    // A: 128 rows x 32 k -> 4 threads/row, 8 elems each
    const int am  = tid >> 2;
    const int akc = (tid & 3) * 8;
    // B: 32 rows (k) x 128 n -> 16 threads/row, 8 elems each
    const int bc  = tid >> 4;
    const int bnc = (tid & 15) * 8;

    const __nv_bfloat16* Wrow = W + (size_t)(m0 + am) * DIM;
    const __nv_bfloat16* Xrow = Xb + (size_t)bc * NPIX + n0;

    auto issue = [&](int s, int k0) {
        __nv_bfloat16* as = As + s * (128 * LDA);
        __nv_bfloat16* bs = Bs + s * (32 * LDB);
        cp_async16(&as[am * LDA + akc], Wrow + k0 + akc);
        cp_async16(&bs[bc * LDB + bnc], Xrow + (size_t)k0 * NPIX + bnc);
        cp_commit();
    };

    issue(0, 0);
    issue(1, 32);

    for (int it = 0; it < 16; it++) {
        if (it + 2 < 16) issue((it + 2) & 3, (it + 2) * 32);
        else             cp_commit();          // keep group count advancing
        cp_wait<2>();                          // group `it` complete
        __syncthreads();

        const __nv_bfloat16* Asb = As + (it & 3) * (128 * LDA);
        const __nv_bfloat16* Bsb = Bs + (it & 3) * (32 * LDB);

        #pragma unroll
        for (int ks = 0; ks < 32; ks += 16) {
            unsigned af[2][4], bf[2][4];
            #pragma unroll
            for (int mt = 0; mt < 2; mt++) {
                unsigned addr = smem_u32(
                    &Asb[(wm * 32 + mt * 16 + (lane & 15)) * LDA + ks + (lane >> 4) * 8]);
                ldsm_x4(af[mt], addr);
            }
            #pragma unroll
            for (int half = 0; half < 2; half++) {
                unsigned addr = smem_u32(
                    &Bsb[(ks + (lane & 15)) * LDB + wn * 32 + half * 16 + (lane >> 4) * 8]);
                ldsm_x4_trans(bf[half], addr);
            }
            #pragma unroll
            for (int mt = 0; mt < 2; mt++)
                #pragma unroll
                for (int nt = 0; nt < 4; nt++)
                    mma16816(acc[mt][nt], af[mt],
                             bf[nt >> 1][(nt & 1) * 2], bf[nt >> 1][(nt & 1) * 2 + 1]);
        }
        // no trailing sync: distance-2 issue invariant covers buffer reuse
    }

    // Epilogue. m16n8k16 accumulator layout:
    // c0:(g, tg*2) c1:(g, tg*2+1) c2:(g+8, tg*2) c3:(g+8, tg*2+1)
    const int g  = lane >> 2;
    const int tg = lane & 3;
    #pragma unroll
    for (int mt = 0; mt < 2; mt++) {
        int gm0 = m0 + wm * 32 + mt * 16 + g;
        float bv0 = bias[gm0];
        float bv1 = bias[gm0 + 8];
        #pragma unroll
        for (int nt = 0; nt < 4; nt++) {
            int n = n0 + wn * 32 + nt * 8 + tg * 2;
            float r00 = acc[mt][nt][0] + bv0;
            float r01 = acc[mt][nt][1] + bv0;
            float r10 = acc[mt][nt][2] + bv1;
            float r11 = acc[mt][nt][3] + bv1;
            if (BF16OUT) {
                int proj = gm0 >> 9;
                int o    = gm0 & 511;
                __nv_bfloat16* op = outb + ((size_t)proj * BATCH + b) * DIM * NPIX;
                size_t off0 = (size_t)o * NPIX + n;
                size_t off1 = off0 + (size_t)8 * NPIX;
                *(__nv_bfloat162*)&op[off0] = __floats2bfloat162_rn(r00, r01);
                *(__nv_bfloat162*)&op[off1] = __floats2bfloat162_rn(r10, r11);
            } else {
                size_t off0 = (size_t)b * DIM * NPIX + (size_t)gm0 * NPIX + n;
                size_t off1 = off0 + (size_t)8 * NPIX;
                float2 x0 = *(const float2*)&resid[off0];
                float2 x1 = *(const float2*)&resid[off1];
                float2 w0, w1;
                w0.x = r00 + x0.x; w0.y = r01 + x0.y;
                w1.x = r10 + x1.x; w1.y = r11 + x1.y;
                *(float2*)&outf[off0] = w0;
                *(float2*)&outf[off1] = w1;
            }
        }
    }
}

// ---------------------------------------------------------------------------
// Tensor-core flash attention (R11 — validated at 159.7us total):
// 4-stage cp.async K/V (64-key tiles), one sync per tile, issue-before-wait,
// P in registers, fixed-shift softmax with Schraudolph exp2.
// Q,K,V bf16 [B*NH][64 d][1024 n]. log2e/8 folded into Q projection.
// 256 threads; warp w owns query rows [w*16, w*16+16).
// ---------------------------------------------------------------------------
#define TI 128
#define TJ 64
#define LDQ 136
#define LDK 72
#define LDV 72
#define LDP 72
#define ASTG 4
#define ATTN_SMEM_ELEMS (64 * LDQ + ASTG * 64 * LDK + ASTG * 64 * LDV)

__global__ __launch_bounds__(256, 2)
void attn_mma(const __nv_bfloat16* __restrict__ Q,
              const __nv_bfloat16* __restrict__ K,
              const __nv_bfloat16* __restrict__ V,
              __nv_bfloat16* __restrict__ AO)
{
    extern __shared__ __nv_bfloat16 smb[];
    __nv_bfloat16* sQ   = smb;                         // [64][LDQ]
    __nv_bfloat16* sK   = sQ + 64 * LDQ;               // [ASTG][64][LDK]
    __nv_bfloat16* sV   = sK + ASTG * 64 * LDK;        // [ASTG][64][LDV]
    __nv_bfloat16* sEpi = sK;                          // epilogue alias (stages 0-1)

    const int tid  = threadIdx.x;
    const int lane = tid & 31;
    const int warp = tid >> 5;
    const int i0   = warp * 16;
    const int g    = lane >> 2;
    const int tg   = lane & 3;
    const int n0   = blockIdx.x * TI;

    const size_t base = ((size_t)blockIdx.z * NH + blockIdx.y) * (size_t)HD * NPIX;
    const __nv_bfloat16* Qp = Q + base;
    const __nv_bfloat16* Kp = K + base;
    const __nv_bfloat16* Vp = V + base;

    // Load Q tile [64][128]
    #pragma unroll
    for (int it = tid; it < 1024; it += 256) {
        int d = it >> 4, c = it & 15;
        *(uint4*)&sQ[d * LDQ + c * 8] =
            *(const uint4*)&Qp[(size_t)d * NPIX + n0 + c * 8];
    }

    auto issueKV = [&](int s, int j0) {
        __nv_bfloat16* ks = sK + s * (64 * LDK);
        __nv_bfloat16* vs = sV + s * (64 * LDV);
        #pragma unroll
        for (int it = tid; it < 512; it += 256) {
            int d = it >> 3, c = it & 7;
            cp_async16(&ks[d * LDK + c * 8], Kp + (size_t)d * NPIX + j0 + c * 8);
            cp_async16(&vs[d * LDV + c * 8], Vp + (size_t)d * NPIX + j0 + c * 8);
        }
        cp_commit();
    };

    issueKV(0, 0);
    issueKV(1, TJ);
    __syncthreads();                 // Q visible

    // Hoisted Q fragments (invariant across KV tiles)
    unsigned aq[4][4];
    #pragma unroll
    for (int k8 = 0; k8 < 4; k8++) {
        unsigned addr = smem_u32(
            &sQ[(k8 * 16 + (lane & 7) + ((lane >> 4) << 3)) * LDQ +
                i0 + ((lane >> 3) & 1) * 8]);
        ldsm_x4_trans(aq[k8], addr);
    }

    float l_h[2], O[8][4];
    l_h[0] = l_h[1] = 0.f;
    #pragma unroll
    for (int dt = 0; dt < 8; dt++)
        #pragma unroll
        for (int r = 0; r < 4; r++) O[dt][r] = 0.f;

    for (int kt = 0; kt < 16; kt++) {
        if (kt + 2 < 16) issueKV((kt + 2) & 3, (kt + 2) * TJ);
        else             cp_commit();
        cp_wait<2>();
        __syncthreads();

        const __nv_bfloat16* sKb = sK + (kt & 3) * (64 * LDK);
        const __nv_bfloat16* sVb = sV + (kt & 3) * (64 * LDV);

        // GEMM1: S[16 i][64 j] = Q^T K
        float S[8][4];
        #pragma unroll
        for (int nt = 0; nt < 8; nt++)
            #pragma unroll
            for (int r = 0; r < 4; r++) S[nt][r] = 0.f;

        #pragma unroll
        for (int k8 = 0; k8 < 4; k8++) {
            unsigned bk[4][4];
            #pragma unroll
            for (int jb = 0; jb < 4; jb++) {
                unsigned addr = smem_u32(
                    &sKb[(k8 * 16 + (lane & 15)) * LDK + jb * 16 + (lane >> 4) * 8]);
                ldsm_x4_trans(bk[jb], addr);
            }
            #pragma unroll
            for (int nt = 0; nt < 8; nt++)
                mma16816(S[nt], aq[k8],
                         bk[nt >> 1][(nt & 1) * 2], bk[nt >> 1][(nt & 1) * 2 + 1]);
        }

        // Fixed-shift softmax, 2-instruction exp2; pack P into GEMM2 A-frags.
        unsigned pa[4][4];
        float rs0 = 0.f, rs1 = 0.f;
        #pragma unroll
        for (int nt = 0; nt < 8; nt++) {
            float p0 = sexp2(S[nt][0]);
            float p1 = sexp2(S[nt][1]);
            float p2 = sexp2(S[nt][2]);
            float p3 = sexp2(S[nt][3]);
            rs0 += p0 + p1;
            rs1 += p2 + p3;
            pa[nt >> 1][(nt & 1) * 2]     = pack_bf16x2(p0, p1);
            pa[nt >> 1][(nt & 1) * 2 + 1] = pack_bf16x2(p2, p3);
        }
        rs0 += __shfl_xor_sync(0xffffffffu, rs0, 1);
        rs0 += __shfl_xor_sync(0xffffffffu, rs0, 2);
        rs1 += __shfl_xor_sync(0xffffffffu, rs1, 1);
        rs1 += __shfl_xor_sync(0xffffffffu, rs1, 2);
        l_h[0] += rs0;
        l_h[1] += rs1;

        // GEMM2: O[16 i][64 d] += P V^T  (A from registers)
        #pragma unroll
        for (int k8 = 0; k8 < 4; k8++) {
            unsigned bv[4][4];
            #pragma unroll
            for (int db = 0; db < 4; db++) {
                unsigned addr = smem_u32(
                    &sVb[(db * 16 + (lane & 15)) * LDV + k8 * 16 + (lane >> 4) * 8]);
                ldsm_x4(bv[db], addr);
            }
            #pragma unroll
            for (int dt = 0; dt < 8; dt++)
                mma16816(O[dt], pa[k8],
                         bv[dt >> 1][dt & 1], bv[dt >> 1][(dt & 1) + 2]);
        }
        // no trailing sync: distance-2 issue invariant covers buffer reuse
    }

    // Scale by 1/l, stage O bf16 [i][d] in sEpi (KV stages 0-1 only)
    float rl0 = 1.f / l_h[0];
    float rl1 = 1.f / l_h[1];
    #pragma unroll
    for (int dt = 0; dt < 8; dt++) {
        *(__nv_bfloat162*)&sEpi[(i0 + g) * LDP + dt * 8 + tg * 2] =
            __floats2bfloat162_rn(O[dt][0] * rl0, O[dt][1] * rl0);
        *(__nv_bfloat162*)&sEpi[(i0 + g + 8) * LDP + dt * 8 + tg * 2] =
            __floats2bfloat162_rn(O[dt][2] * rl1, O[dt][3] * rl1);
    }
    __syncthreads();

    // Transpose out: AO[d][n0 + i], 8 bf16 per store
    __nv_bfloat16* AOp = AO + base;
    #pragma unroll
    for (int it = tid; it < 1024; it += 256) {
        int d  = it & 63;
        int ic = it >> 6;
        __nv_bfloat16 t[8];
        #pragma unroll
        for (int u = 0; u < 8; u++)
            t[u] = sEpi[(ic * 8 + u) * LDP + d];
        *(uint4*)&AOp[(size_t)d * NPIX + n0 + ic * 8] = *(uint4*)t;
    }
}

// ---------------------------------------------------------------------------
extern "C" void kernel_launch(void* const* d_in, const int* in_sizes, int n_in,
                              void* d_out, int out_size)
{
    const float* x  = (const float*)d_in[0];
    const float* Wq = (const float*)d_in[1];
    const float* bq = (const float*)d_in[2];
    const float* Wk = (const float*)d_in[3];
    const float* bk = (const float*)d_in[4];
    const float* Wv = (const float*)d_in[5];
    const float* bv = (const float*)d_in[6];
    const float* Wo = (const float*)d_in[7];
    const float* bo = (const float*)d_in[8];
    float* out = (float*)d_out;

    __nv_bfloat16 *xb, *wb, *qkv, *aob;
    float* bqkv;
    cudaGetSymbolAddress((void**)&xb,   g_xb);
    cudaGetSymbolAddress((void**)&wb,   g_wb);
    cudaGetSymbolAddress((void**)&bqkv, g_bqkv);
    cudaGetSymbolAddress((void**)&qkv,  g_qkv);
    cudaGetSymbolAddress((void**)&aob,  g_aob);

    // 1/sqrt(64) * log2(e): folded into Wq/bq so softmax runs in base 2
    const float qscale = 0.125f * 1.4426950408889634f;

    f2bf<<<PLANE / 4 / 256, 256>>>(x, xb, PLANE / 4);
    f2bf_w<<<4 * DIM * DIM / 4 / 256, 256>>>(Wq, Wk, Wv, Wo, wb, qscale);
    pack_bias<<<6, 256>>>(bq, bk, bv, bqkv, qscale);

    cudaFuncSetAttribute(gemm_tc<true>, cudaFuncAttributeMaxDynamicSharedMemorySize,
                         GEMM_SMEM_BYTES);
    cudaFuncSetAttribute(gemm_tc<false>, cudaFuncAttributeMaxDynamicSharedMemorySize,
                         GEMM_SMEM_BYTES);

    // Fused QKV projection: M = 1536 stacked
    dim3 qkv_grid(NPIX / 128, 3 * DIM / 128, BATCH);   // (8, 12, 8)
    gemm_tc<true><<<qkv_grid, 512, GEMM_SMEM_BYTES>>>(wb, xb, bqkv, nullptr,
                                                      nullptr, qkv);

    const int attn_smem = ATTN_SMEM_ELEMS * (int)sizeof(__nv_bfloat16);
    cudaFuncSetAttribute(attn_mma, cudaFuncAttributeMaxDynamicSharedMemorySize,
                         attn_smem);
    dim3 attn_grid(NPIX / TI, NH, BATCH);              // (8, 8, 8)
    attn_mma<<<attn_grid, 256, attn_smem>>>(qkv, qkv + PLANE, qkv + 2 * PLANE, aob);

    dim3 o_grid(NPIX / 128, DIM / 128, BATCH);         // (8, 4, 8)
    gemm_tc<false><<<o_grid, 512, GEMM_SMEM_BYTES>>>(wb + 3 * DIM * DIM, aob, bo,
                                                     x, out, nullptr);
}

// round 14
// speedup vs baseline: 1.2669x; 1.0131x over previous
#include <cuda_runtime.h>
#include <cuda_bf16.h>
#include <math.h>

// Problem constants
// x:  [B=8, C=512, H=32, W=32] -> [8, 512, 1024]
// W*: [512, 512], b*: [512]
// heads = 8, head_dim = 64, N = 1024

#define BATCH 8
#define DIM 512
#define NPIX 1024
#define NH 8
#define HD 64
#define PLANE (BATCH * DIM * NPIX)   // 4,194,304 elements

// Scratch (static __device__ globals: allocation-guard safe)
__device__ __nv_bfloat16 g_xb[PLANE];
__device__ __nv_bfloat16 g_wb[4 * DIM * DIM];   // Wq|Wk|Wv|Wo (Wq pre-scaled)
__device__ float         g_bqkv[3 * DIM];       // bq*qscale | bk | bv
__device__ __nv_bfloat16 g_qkv[3 * PLANE];      // Q | K | V bf16
__device__ __nv_bfloat16 g_aob[PLANE];          // attention out bf16

// ---------------------------------------------------------------------------
// Fused conversion kernel: one launch does x->bf16, W*->bf16 (Wq scaled),
// and bias packing. Work partitioned by blockIdx.x:
//   [0, 4096)         : x     (1,048,576 float4s)
//   [4096, 5120)      : W     (262,144 float4s across 4 matrices)
//   [5120]            : bias  (1536 floats)
// ---------------------------------------------------------------------------
#define CONV_XBLK  4096
#define CONV_WBLK  1024
#define CONV_GRID  (CONV_XBLK + CONV_WBLK + 1)

__global__ void convert_all(const float* __restrict__ x,
                            const float* __restrict__ Wq, const float* __restrict__ Wk,
                            const float* __restrict__ Wv, const float* __restrict__ Wo,
                            const float* __restrict__ bq, const float* __restrict__ bk,
                            const float* __restrict__ bv,
                            __nv_bfloat16* __restrict__ xb,
                            __nv_bfloat16* __restrict__ wb,
                            float* __restrict__ bqkv, float qs)
{
    const int blk = blockIdx.x;
    const int tid = threadIdx.x;
    if (blk < CONV_XBLK) {
        int i = blk * 256 + tid;
        float4 v = ((const float4*)x)[i];
        ((__nv_bfloat162*)xb)[i * 2]     = __floats2bfloat162_rn(v.x, v.y);
        ((__nv_bfloat162*)xb)[i * 2 + 1] = __floats2bfloat162_rn(v.z, v.w);
    } else if (blk < CONV_XBLK + CONV_WBLK) {
        const int n4m = DIM * DIM / 4;               // 65536
        int i = (blk - CONV_XBLK) * 256 + tid;       // < 262144
        int m = i / n4m, r = i - m * n4m;
        const float* src = (m == 0) ? Wq : (m == 1) ? Wk : (m == 2) ? Wv : Wo;
        float s = (m == 0) ? qs : 1.f;
        float4 v = ((const float4*)src)[r];
        ((__nv_bfloat162*)wb)[i * 2]     = __floats2bfloat162_rn(v.x * s, v.y * s);
        ((__nv_bfloat162*)wb)[i * 2 + 1] = __floats2bfloat162_rn(v.z * s, v.w * s);
    } else {
        // 1536 floats with 256 threads: 6 per thread
        #pragma unroll
        for (int u = 0; u < 6; u++) {
            int i = u * 256 + tid;
            float v;
            if (i < DIM)            v = bq[i] * qs;
            else if (i < 2 * DIM)   v = bk[i - DIM];
            else                    v = bv[i - 2 * DIM];
            bqkv[i] = v;
        }
    }
}

// ---------------------------------------------------------------------------
// Tensor-core / async-copy helpers
// ---------------------------------------------------------------------------
__device__ __forceinline__ unsigned smem_u32(const void* p)
{
    return (unsigned)__cvta_generic_to_shared(p);
}

__device__ __forceinline__ void cp_async16(void* smem_dst, const void* gmem_src)
{
    asm volatile("cp.async.cg.shared.global [%0], [%1], 16;\n"
                 :: "r"(smem_u32(smem_dst)), "l"(gmem_src));
}
__device__ __forceinline__ void cp_commit()
{
    asm volatile("cp.async.commit_group;\n");
}
template<int N>
__device__ __forceinline__ void cp_wait()
{
    asm volatile("cp.async.wait_group %0;\n" :: "n"(N));
}

__device__ __forceinline__ void ldsm_x4(unsigned* r, unsigned addr)
{
    asm volatile("ldmatrix.sync.aligned.m8n8.x4.shared.b16 {%0,%1,%2,%3}, [%4];\n"
                 : "=r"(r[0]), "=r"(r[1]), "=r"(r[2]), "=r"(r[3]) : "r"(addr));
}

__device__ __forceinline__ void ldsm_x4_trans(unsigned* r, unsigned addr)
{
    asm volatile("ldmatrix.sync.aligned.m8n8.x4.trans.shared.b16 {%0,%1,%2,%3}, [%4];\n"
                 : "=r"(r[0]), "=r"(r[1]), "=r"(r[2]), "=r"(r[3]) : "r"(addr));
}

__device__ __forceinline__ void mma16816(float* d, const unsigned* a,
                                         unsigned b0, unsigned b1)
{
    asm volatile(
        "mma.sync.aligned.m16n8k16.row.col.f32.bf16.bf16.f32 "
        "{%0,%1,%2,%3}, {%4,%5,%6,%7}, {%8,%9}, {%0,%1,%2,%3};\n"
        : "+f"(d[0]), "+f"(d[1]), "+f"(d[2]), "+f"(d[3])
        : "r"(a[0]), "r"(a[1]), "r"(a[2]), "r"(a[3]), "r"(b0), "r"(b1));
}

// Schraudolph exp2: 2 instructions. Max rel err ~3%; softmax normalization
// cancels the common mode and P is rounded to bf16 anyway.
__device__ __forceinline__ float sexp2(float t)
{
    float f = fmaf(t, 8388608.f, 1064866805.f);   // t*2^23 + (127<<23 - 486411)
    return __int_as_float((int)f);
}

__device__ __forceinline__ unsigned pack_bf16x2(float a, float b)
{
    __nv_bfloat162 t = __floats2bfloat162_rn(a, b);
    return *(unsigned*)&t;
}

// ---------------------------------------------------------------------------
// bf16 tensor-core GEMM, R14: R13 layout/roles (512 thr, 32x32 warp tile,
// BK=32) with GSTG 4->6 and issue distance 2->4 (d <= S-2 invariant: at
// issue(it+4), sync(it-1) has proven all warps finished compute(it-2) =
// the stage being overwritten).
// acc[m][n] = sum_c W[m][c] X[b][c][n];  epilogue = acc + bias[m]
// BF16OUT=true:  M=1536 stacked QKV -> outb[(proj*BATCH+b)][o][n] bf16.
// BF16OUT=false: M=512; fp32 out + residual.
// ---------------------------------------------------------------------------
#define LDA 40
#define LDB 136
#define GSTG 6
#define GDIST 4
#define GSTAGE_ELEMS (128 * LDA + 32 * LDB)
#define GEMM_SMEM_BYTES (GSTG * GSTAGE_ELEMS * 2)   // 113,664 B

template<bool BF16OUT>
__global__ __launch_bounds__(512, 2)
void gemm_tc(const __nv_bfloat16* __restrict__ W,
             const __nv_bfloat16* __restrict__ X,
             const float* __restrict__ bias,
             const float* __restrict__ resid,
             float* __restrict__ outf,
             __nv_bfloat16* __restrict__ outb)
{
    extern __shared__ __nv_bfloat16 gsm[];

    const int b  = blockIdx.z;
    const int m0 = blockIdx.y * 128;
    const int n0 = blockIdx.x * 128;

    const __nv_bfloat16* Xb = X + (size_t)b * DIM * NPIX;

    const int tid  = threadIdx.x;
    const int lane = tid & 31;
    const int warp = tid >> 5;       // 0..15
    const int wm   = warp >> 2;      // 0..3: m sub-tile (32 rows)
    const int wn   = warp & 3;       // 0..3: n sub-tile (32 cols)

    float acc[2][4][4];
    #pragma unroll
    for (int mt = 0; mt < 2; mt++)
        #pragma unroll
        for (int nt = 0; nt < 4; nt++)
            #pragma unroll
            for (int r = 0; r < 4; r++) acc[mt][nt][r] = 0.f;

    // Copy roles (512 threads, 1 cp.async16 each per operand):
    const int am  = tid >> 2;
    const int akc = (tid & 3) * 8;
    const int bc  = tid >> 4;
    const int bnc = (tid & 15) * 8;

    const __nv_bfloat16* Wrow = W + (size_t)(m0 + am) * DIM;
    const __nv_bfloat16* Xrow = Xb + (size_t)bc * NPIX + n0;

    auto issue = [&](int s, int k0) {
        __nv_bfloat16* as = gsm + s * GSTAGE_ELEMS;
        __nv_bfloat16* bs = as + 128 * LDA;
        cp_async16(&as[am * LDA + akc], Wrow + k0 + akc);
        cp_async16(&bs[bc * LDB + bnc], Xrow + (size_t)k0 * NPIX + bnc);
        cp_commit();
    };

    #pragma unroll
    for (int p = 0; p < GDIST; p++) issue(p, p * 32);

    for (int it = 0; it < 16; it++) {
        if (it + GDIST < 16) {
            int s = (it + GDIST) % GSTG;
            issue(s, (it + GDIST) * 32);
        } else {
            cp_commit();                       // keep group count advancing
        }
        cp_wait<GDIST>();                      // group `it` complete
        __syncthreads();

        const __nv_bfloat16* Asb = gsm + (it % GSTG) * GSTAGE_ELEMS;
        const __nv_bfloat16* Bsb = Asb + 128 * LDA;

        #pragma unroll
        for (int ks = 0; ks < 32; ks += 16) {
            unsigned af[2][4], bf[2][4];
            #pragma unroll
            for (int mt = 0; mt < 2; mt++) {
                unsigned addr = smem_u32(
                    &Asb[(wm * 32 + mt * 16 + (lane & 15)) * LDA + ks + (lane >> 4) * 8]);
                ldsm_x4(af[mt], addr);
            }
            #pragma unroll
            for (int half = 0; half < 2; half++) {
                unsigned addr = smem_u32(
                    &Bsb[(ks + (lane & 15)) * LDB + wn * 32 + half * 16 + (lane >> 4) * 8]);
                ldsm_x4_trans(bf[half], addr);
            }
            #pragma unroll
            for (int mt = 0; mt < 2; mt++)
                #pragma unroll
                for (int nt = 0; nt < 4; nt++)
                    mma16816(acc[mt][nt], af[mt],
                             bf[nt >> 1][(nt & 1) * 2], bf[nt >> 1][(nt & 1) * 2 + 1]);
        }
        // no trailing sync: distance-4/6-stage invariant covers buffer reuse
    }

    // Epilogue. m16n8k16 accumulator layout:
    // c0:(g, tg*2) c1:(g, tg*2+1) c2:(g+8, tg*2) c3:(g+8, tg*2+1)
    const int g  = lane >> 2;
    const int tg = lane & 3;
    #pragma unroll
    for (int mt = 0; mt < 2; mt++) {
        int gm0 = m0 + wm * 32 + mt * 16 + g;
        float bv0 = bias[gm0];
        float bv1 = bias[gm0 + 8];
        #pragma unroll
        for (int nt = 0; nt < 4; nt++) {
            int n = n0 + wn * 32 + nt * 8 + tg * 2;
            float r00 = acc[mt][nt][0] + bv0;
            float r01 = acc[mt][nt][1] + bv0;
            float r10 = acc[mt][nt][2] + bv1;
            float r11 = acc[mt][nt][3] + bv1;
            if (BF16OUT) {
                int proj = gm0 >> 9;
                int o    = gm0 & 511;
                __nv_bfloat16* op = outb + ((size_t)proj * BATCH + b) * DIM * NPIX;
                size_t off0 = (size_t)o * NPIX + n;
                size_t off1 = off0 + (size_t)8 * NPIX;
                *(__nv_bfloat162*)&op[off0] = __floats2bfloat162_rn(r00, r01);
                *(__nv_bfloat162*)&op[off1] = __floats2bfloat162_rn(r10, r11);
            } else {
                size_t off0 = (size_t)b * DIM * NPIX + (size_t)gm0 * NPIX + n;
                size_t off1 = off0 + (size_t)8 * NPIX;
                float2 x0 = *(const float2*)&resid[off0];
                float2 x1 = *(const float2*)&resid[off1];
                float2 w0, w1;
                w0.x = r00 + x0.x; w0.y = r01 + x0.y;
                w1.x = r10 + x1.x; w1.y = r11 + x1.y;
                *(float2*)&outf[off0] = w0;
                *(float2*)&outf[off1] = w1;
            }
        }
    }
}

// ---------------------------------------------------------------------------
// Tensor-core flash attention (R11/R13 — validated):
// 4-stage cp.async K/V (64-key tiles), one sync per tile, issue-before-wait,
// P in registers, fixed-shift softmax with Schraudolph exp2.
// Q,K,V bf16 [B*NH][64 d][1024 n]. log2e/8 folded into Q projection.
// 256 threads; warp w owns query rows [w*16, w*16+16).
// ---------------------------------------------------------------------------
#define TI 128
#define TJ 64
#define LDQ 136
#define LDK 72
#define LDV 72
#define LDP 72
#define ASTG 4
#define ATTN_SMEM_ELEMS (64 * LDQ + ASTG * 64 * LDK + ASTG * 64 * LDV)

__global__ __launch_bounds__(256, 2)
void attn_mma(const __nv_bfloat16* __restrict__ Q,
              const __nv_bfloat16* __restrict__ K,
              const __nv_bfloat16* __restrict__ V,
              __nv_bfloat16* __restrict__ AO)
{
    extern __shared__ __nv_bfloat16 smb[];
    __nv_bfloat16* sQ   = smb;                         // [64][LDQ]
    __nv_bfloat16* sK   = sQ + 64 * LDQ;               // [ASTG][64][LDK]
    __nv_bfloat16* sV   = sK + ASTG * 64 * LDK;        // [ASTG][64][LDV]
    __nv_bfloat16* sEpi = sK;                          // epilogue alias (stages 0-1)

    const int tid  = threadIdx.x;
    const int lane = tid & 31;
    const int warp = tid >> 5;
    const int i0   = warp * 16;
    const int g    = lane >> 2;
    const int tg   = lane & 3;
    const int n0   = blockIdx.x * TI;

    const size_t base = ((size_t)blockIdx.z * NH + blockIdx.y) * (size_t)HD * NPIX;
    const __nv_bfloat16* Qp = Q + base;
    const __nv_bfloat16* Kp = K + base;
    const __nv_bfloat16* Vp = V + base;

    // Load Q tile [64][128]
    #pragma unroll
    for (int it = tid; it < 1024; it += 256) {
        int d = it >> 4, c = it & 15;
        *(uint4*)&sQ[d * LDQ + c * 8] =
            *(const uint4*)&Qp[(size_t)d * NPIX + n0 + c * 8];
    }

    auto issueKV = [&](int s, int j0) {
        __nv_bfloat16* ks = sK + s * (64 * LDK);
        __nv_bfloat16* vs = sV + s * (64 * LDV);
        #pragma unroll
        for (int it = tid; it < 512; it += 256) {
            int d = it >> 3, c = it & 7;
            cp_async16(&ks[d * LDK + c * 8], Kp + (size_t)d * NPIX + j0 + c * 8);
            cp_async16(&vs[d * LDV + c * 8], Vp + (size_t)d * NPIX + j0 + c * 8);
        }
        cp_commit();
    };

    issueKV(0, 0);
    issueKV(1, TJ);
    __syncthreads();                 // Q visible

    // Hoisted Q fragments (invariant across KV tiles)
    unsigned aq[4][4];
    #pragma unroll
    for (int k8 = 0; k8 < 4; k8++) {
        unsigned addr = smem_u32(
            &sQ[(k8 * 16 + (lane & 7) + ((lane >> 4) << 3)) * LDQ +
                i0 + ((lane >> 3) & 1) * 8]);
        ldsm_x4_trans(aq[k8], addr);
    }

    float l_h[2], O[8][4];
    l_h[0] = l_h[1] = 0.f;
    #pragma unroll
    for (int dt = 0; dt < 8; dt++)
        #pragma unroll
        for (int r = 0; r < 4; r++) O[dt][r] = 0.f;

    for (int kt = 0; kt < 16; kt++) {
        if (kt + 2 < 16) issueKV((kt + 2) & 3, (kt + 2) * TJ);
        else             cp_commit();
        cp_wait<2>();
        __syncthreads();

        const __nv_bfloat16* sKb = sK + (kt & 3) * (64 * LDK);
        const __nv_bfloat16* sVb = sV + (kt & 3) * (64 * LDV);

        // GEMM1: S[16 i][64 j] = Q^T K
        float S[8][4];
        #pragma unroll
        for (int nt = 0; nt < 8; nt++)
            #pragma unroll
            for (int r = 0; r < 4; r++) S[nt][r] = 0.f;

        #pragma unroll
        for (int k8 = 0; k8 < 4; k8++) {
            unsigned bk[4][4];
            #pragma unroll
            for (int jb = 0; jb < 4; jb++) {
                unsigned addr = smem_u32(
                    &sKb[(k8 * 16 + (lane & 15)) * LDK + jb * 16 + (lane >> 4) * 8]);
                ldsm_x4_trans(bk[jb], addr);
            }
            #pragma unroll
            for (int nt = 0; nt < 8; nt++)
                mma16816(S[nt], aq[k8],
                         bk[nt >> 1][(nt & 1) * 2], bk[nt >> 1][(nt & 1) * 2 + 1]);
        }

        // Fixed-shift softmax, 2-instruction exp2; pack P into GEMM2 A-frags.
        unsigned pa[4][4];
        float rs0 = 0.f, rs1 = 0.f;
        #pragma unroll
        for (int nt = 0; nt < 8; nt++) {
            float p0 = sexp2(S[nt][0]);
            float p1 = sexp2(S[nt][1]);
            float p2 = sexp2(S[nt][2]);
            float p3 = sexp2(S[nt][3]);
            rs0 += p0 + p1;
            rs1 += p2 + p3;
            pa[nt >> 1][(nt & 1) * 2]     = pack_bf16x2(p0, p1);
            pa[nt >> 1][(nt & 1) * 2 + 1] = pack_bf16x2(p2, p3);
        }
        rs0 += __shfl_xor_sync(0xffffffffu, rs0, 1);
        rs0 += __shfl_xor_sync(0xffffffffu, rs0, 2);
        rs1 += __shfl_xor_sync(0xffffffffu, rs1, 1);
        rs1 += __shfl_xor_sync(0xffffffffu, rs1, 2);
        l_h[0] += rs0;
        l_h[1] += rs1;

        // GEMM2: O[16 i][64 d] += P V^T  (A from registers)
        #pragma unroll
        for (int k8 = 0; k8 < 4; k8++) {
            unsigned bv[4][4];
            #pragma unroll
            for (int db = 0; db < 4; db++) {
                unsigned addr = smem_u32(
                    &sVb[(db * 16 + (lane & 15)) * LDV + k8 * 16 + (lane >> 4) * 8]);
                ldsm_x4(bv[db], addr);
            }
            #pragma unroll
            for (int dt = 0; dt < 8; dt++)
                mma16816(O[dt], pa[k8],
                         bv[dt >> 1][dt & 1], bv[dt >> 1][(dt & 1) + 2]);
        }
        // no trailing sync: distance-2 issue invariant covers buffer reuse
    }

    // Scale by 1/l, stage O bf16 [i][d] in sEpi (KV stages 0-1 only)
    float rl0 = 1.f / l_h[0];
    float rl1 = 1.f / l_h[1];
    #pragma unroll
    for (int dt = 0; dt < 8; dt++) {
        *(__nv_bfloat162*)&sEpi[(i0 + g) * LDP + dt * 8 + tg * 2] =
            __floats2bfloat162_rn(O[dt][0] * rl0, O[dt][1] * rl0);
        *(__nv_bfloat162*)&sEpi[(i0 + g + 8) * LDP + dt * 8 + tg * 2] =
            __floats2bfloat162_rn(O[dt][2] * rl1, O[dt][3] * rl1);
    }
    __syncthreads();

    // Transpose out: AO[d][n0 + i], 8 bf16 per store
    __nv_bfloat16* AOp = AO + base;
    #pragma unroll
    for (int it = tid; it < 1024; it += 256) {
        int d  = it & 63;
        int ic = it >> 6;
        __nv_bfloat16 t[8];
        #pragma unroll
        for (int u = 0; u < 8; u++)
            t[u] = sEpi[(ic * 8 + u) * LDP + d];
        *(uint4*)&AOp[(size_t)d * NPIX + n0 + ic * 8] = *(uint4*)t;
    }
}

// ---------------------------------------------------------------------------
extern "C" void kernel_launch(void* const* d_in, const int* in_sizes, int n_in,
                              void* d_out, int out_size)
{
    const float* x  = (const float*)d_in[0];
    const float* Wq = (const float*)d_in[1];
    const float* bq = (const float*)d_in[2];
    const float* Wk = (const float*)d_in[3];
    const float* bk = (const float*)d_in[4];
    const float* Wv = (const float*)d_in[5];
    const float* bv = (const float*)d_in[6];
    const float* Wo = (const float*)d_in[7];
    const float* bo = (const float*)d_in[8];
    float* out = (float*)d_out;

    __nv_bfloat16 *xb, *wb, *qkv, *aob;
    float* bqkv;
    cudaGetSymbolAddress((void**)&xb,   g_xb);
    cudaGetSymbolAddress((void**)&wb,   g_wb);
    cudaGetSymbolAddress((void**)&bqkv, g_bqkv);
    cudaGetSymbolAddress((void**)&qkv,  g_qkv);
    cudaGetSymbolAddress((void**)&aob,  g_aob);

    // 1/sqrt(64) * log2(e): folded into Wq/bq so softmax runs in base 2
    const float qscale = 0.125f * 1.4426950408889634f;

    convert_all<<<CONV_GRID, 256>>>(x, Wq, Wk, Wv, Wo, bq, bk, bv,
                                    xb, wb, bqkv, qscale);

    cudaFuncSetAttribute(gemm_tc<true>, cudaFuncAttributeMaxDynamicSharedMemorySize,
                         GEMM_SMEM_BYTES);
    cudaFuncSetAttribute(gemm_tc<false>, cudaFuncAttributeMaxDynamicSharedMemorySize,
                         GEMM_SMEM_BYTES);

    // Fused QKV projection: M = 1536 stacked
    dim3 qkv_grid(NPIX / 128, 3 * DIM / 128, BATCH);   // (8, 12, 8)
    gemm_tc<true><<<qkv_grid, 512, GEMM_SMEM_BYTES>>>(wb, xb, bqkv, nullptr,
                                                      nullptr, qkv);

    const int attn_smem = ATTN_SMEM_ELEMS * (int)sizeof(__nv_bfloat16);
    cudaFuncSetAttribute(attn_mma, cudaFuncAttributeMaxDynamicSharedMemorySize,
                         attn_smem);
    dim3 attn_grid(NPIX / TI, NH, BATCH);              // (8, 8, 8)
    attn_mma<<<attn_grid, 256, attn_smem>>>(qkv, qkv + PLANE, qkv + 2 * PLANE, aob);

    dim3 o_grid(NPIX / 128, DIM / 128, BATCH);         // (8, 4, 8)
    gemm_tc<false><<<o_grid, 512, GEMM_SMEM_BYTES>>>(wb + 3 * DIM * DIM, aob, bo,
                                                     x, out, nullptr);
}